// round 12
// baseline (speedup 1.0000x reference)
#include <cuda_runtime.h>

#define ATT_H 128
#define KVH   256
#define NB    2
#define NS    1024
#define NQ    512
#define SK2   32
#define NSC   16                        // pgemm split-s count
#define NROWS (NB*NS + NB*NQ)           // 3072 projection rows

// scratch (no allocations allowed)
__device__ float g_proj_kv[NB*NS*ATT_H];
__device__ float g_proj_q [NB*NQ*ATT_H];
__device__ float g_pp     [2*NROWS*ATT_H];
__device__ float g_E      [NB*NQ*NS];      // [b][q][s] raw exp(score)
__device__ float g_ET     [NB*NS*NQ];      // [b][s][q] transposed copy
__device__ float g_part   [NSC*NB*NQ*KVH]; // split-s partial GEMM results
__device__ float g_inv    [NB*NQ];

__device__ __forceinline__ float fast_tanh(float x){ float y; asm("tanh.approx.f32 %0, %1;" : "=f"(y) : "f"(x)); return y; }
__device__ __forceinline__ float fast_ex2 (float x){ float y; asm("ex2.approx.f32 %0, %1;"  : "=f"(y) : "f"(x)); return y; }

__device__ __forceinline__ float2 ffma2(float2 a, float2 b, float2 c) {
    float2 d;
    asm("fma.rn.f32x2 %0, %1, %2, %3;"
        : "=l"(reinterpret_cast<unsigned long long&>(d))
        : "l"(reinterpret_cast<unsigned long long&>(a)),
          "l"(reinterpret_cast<unsigned long long&>(b)),
          "l"(reinterpret_cast<unsigned long long&>(c)));
    return d;
}

__device__ __forceinline__ void cp16(void* dst, const void* src) {
    unsigned d = (unsigned)__cvta_generic_to_shared(dst);
    asm volatile("cp.async.cg.shared.global [%0], [%1], 16;" :: "r"(d), "l"(src));
}
__device__ __forceinline__ void cp_commit() { asm volatile("cp.async.commit_group;"); }
__device__ __forceinline__ void cp_wait0()  { asm volatile("cp.async.wait_group 0;" ::: "memory"); }
__device__ __forceinline__ void cp_wait1()  { asm volatile("cp.async.wait_group 1;" ::: "memory"); }

// ---------------- Kernel 1: proj partials, k-split x2, 256 thr, 4r x 2c tile ----------------
__global__ void __launch_bounds__(256) proj_kernel(
    const float* __restrict__ kv, const float* __restrict__ qy,
    const float* __restrict__ Wkv, const float* __restrict__ Wq)
{
    __shared__ float w_sh [64*64];
    __shared__ float in_T [64*34];

    const int tid = threadIdx.x;
    const int rb  = blockIdx.x;       // 384 = 96 rowblk * 2 ch * 2 kh
    const int kh  = rb & 1;
    const int ch  = (rb >> 1) & 1;
    const int row0g = (rb >> 2) * 32;

    const float *in, *W;
    if (row0g < NB*NS) { in = kv + (size_t)row0g*256;           W = Wkv; }
    else               { in = qy + (size_t)(row0g - NB*NS)*256; W = Wq;  }
    in += kh*128;
    W  += (size_t)kh*128*128;

    const int tx = tid & 31;
    const int ty = tid >> 5;

    float2 acc[4];
    #pragma unroll
    for (int i = 0; i < 4; i++) acc[i] = make_float2(0.f, 0.f);

    float4 wr[4], ir[2];
    #pragma unroll
    for (int j = 0; j < 4; j++) {
        int f4 = tid + 256*j; int kk = f4 >> 4, c4 = f4 & 15;
        wr[j] = *(const float4*)(W + (size_t)kk*128 + ch*64 + c4*4);
    }
    #pragma unroll
    for (int j = 0; j < 2; j++) {
        int f4 = tid + 256*j; int r = f4 >> 4, k4 = f4 & 15;
        ir[j] = *(const float4*)(in + (size_t)r*256 + k4*4);
    }

    for (int kc = 0; kc < 2; kc++) {
        #pragma unroll
        for (int j = 0; j < 4; j++) {
            int f4 = tid + 256*j; int kk = f4 >> 4, c4 = f4 & 15;
            ((float4*)w_sh)[kk*16 + c4] = wr[j];
        }
        #pragma unroll
        for (int j = 0; j < 2; j++) {
            int f4 = tid + 256*j; int r = f4 >> 4, k4 = f4 & 15;
            in_T[(k4*4+0)*34 + r] = ir[j].x;
            in_T[(k4*4+1)*34 + r] = ir[j].y;
            in_T[(k4*4+2)*34 + r] = ir[j].z;
            in_T[(k4*4+3)*34 + r] = ir[j].w;
        }
        __syncthreads();
        if (kc < 1) {
            #pragma unroll
            for (int j = 0; j < 4; j++) {
                int f4 = tid + 256*j; int kk = f4 >> 4, c4 = f4 & 15;
                wr[j] = *(const float4*)(W + (size_t)(64 + kk)*128 + ch*64 + c4*4);
            }
            #pragma unroll
            for (int j = 0; j < 2; j++) {
                int f4 = tid + 256*j; int r = f4 >> 4, k4 = f4 & 15;
                ir[j] = *(const float4*)(in + (size_t)r*256 + 64 + k4*4);
            }
        }
        #pragma unroll 8
        for (int kk = 0; kk < 64; kk++) {
            float2 w2  = *(const float2*)&w_sh[kk*64 + tx*2];
            float2 i01 = *(const float2*)&in_T[kk*34 + ty*4];
            float2 i23 = *(const float2*)&in_T[kk*34 + ty*4 + 2];
            acc[0] = ffma2(w2, make_float2(i01.x, i01.x), acc[0]);
            acc[1] = ffma2(w2, make_float2(i01.y, i01.y), acc[1]);
            acc[2] = ffma2(w2, make_float2(i23.x, i23.x), acc[2]);
            acc[3] = ffma2(w2, make_float2(i23.y, i23.y), acc[3]);
        }
        __syncthreads();
    }

    float* outp = g_pp + (size_t)kh*NROWS*ATT_H + (size_t)(row0g + ty*4)*ATT_H + ch*64 + tx*2;
    #pragma unroll
    for (int ri = 0; ri < 4; ri++)
        *(float2*)(outp + (size_t)ri*ATT_H) = acc[ri];
}

// ---------------- Kernel 1b: combine proj k-halves + bias ----------------
__global__ void __launch_bounds__(256) proj_fix_kernel(
    const float* __restrict__ bkv, const float* __restrict__ bq)
{
    const int idx = blockIdx.x*256 + threadIdx.x;
    const int row = idx >> 5;
    const int c4  = idx & 31;
    float4 a = ((const float4*)g_pp)[idx];
    float4 b = ((const float4*)g_pp)[idx + NROWS*32];
    const float* bias; float* out; int rloc;
    if (row < NB*NS) { bias = bkv; out = g_proj_kv; rloc = row; }
    else             { bias = bq;  out = g_proj_q;  rloc = row - NB*NS; }
    float4 bb = ((const float4*)bias)[c4];
    ((float4*)(out + (size_t)rloc*ATT_H))[c4] =
        make_float4(a.x+b.x+bb.x, a.y+b.y+bb.y, a.z+b.z+bb.z, a.w+b.w+bb.w);
}

// ---------------- Kernel 2: score (monolithic) + ET transpose emit. Grid 2048. ----------------
__global__ void __launch_bounds__(256) score_kernel(
    const float* __restrict__ wv_g, const float* __restrict__ bv_g)
{
    __shared__ float4 pk_sh[64*33];
    __shared__ float4 pq_sh[8*32];
    __shared__ float4 wv_sh[32];
    __shared__ float  ET_sh[64*9];     // [s_local][q] pad 9

    const int tid = threadIdx.x;
    const int bid = blockIdx.x;
    const int st  = bid & 15;
    const int qt  = bid >> 4;
    const int b   = qt >> 6;
    const int q0  = (qt & 63) * 8;
    const int s0  = st * 64;

    const float4* pqsrc = (const float4*)(g_proj_q + (b*NQ + q0)*ATT_H);
    pq_sh[tid] = pqsrc[tid];
    if (tid < 32) wv_sh[tid] = ((const float4*)wv_g)[tid];
    const float4* pksrc = (const float4*)(g_proj_kv + (b*NS + s0)*ATT_H);
    #pragma unroll
    for (int i = 0; i < 8; i++) {
        int f4 = tid + 256*i;
        pk_sh[(f4 >> 5)*33 + (f4 & 31)] = pksrc[f4];
    }
    __syncthreads();

    const float bv = __ldg(bv_g);
    const int sl = tid & 63;
    const int qq = tid >> 6;

    float acc0 = 0.f, acc1 = 0.f;
    const float4* pkp  = pk_sh + sl*33;
    const float4* pq0p = pq_sh + (2*qq    )*32;
    const float4* pq1p = pq_sh + (2*qq + 1)*32;

    #pragma unroll 8
    for (int a4 = 0; a4 < 32; a4++) {
        float4 pk = pkp[a4];
        float4 w  = wv_sh[a4];
        float4 p0 = pq0p[a4];
        float4 p1 = pq1p[a4];
        acc0 += w.x * fast_tanh(pk.x + p0.x);
        acc0 += w.y * fast_tanh(pk.y + p0.y);
        acc0 += w.z * fast_tanh(pk.z + p0.z);
        acc0 += w.w * fast_tanh(pk.w + p0.w);
        acc1 += w.x * fast_tanh(pk.x + p1.x);
        acc1 += w.y * fast_tanh(pk.y + p1.y);
        acc1 += w.z * fast_tanh(pk.z + p1.z);
        acc1 += w.w * fast_tanh(pk.w + p1.w);
    }
    float e0 = fast_ex2((acc0 + bv) * 1.44269504f);
    float e1 = fast_ex2((acc1 + bv) * 1.44269504f);

    // row-major write (for rowsum/out_w)
    float* Eout = g_E + (size_t)(b*NQ + q0 + 2*qq)*NS + s0 + sl;
    Eout[0]  = e0;
    Eout[NS] = e1;

    // transposed write (for pgemm): stage in smem, then coalesced float2
    ET_sh[sl*9 + 2*qq]     = e0;
    ET_sh[sl*9 + 2*qq + 1] = e1;
    __syncthreads();
    {
        int s_local = tid >> 2, qp = tid & 3;
        float2 v = make_float2(ET_sh[s_local*9 + qp*2], ET_sh[s_local*9 + qp*2 + 1]);
        *(float2*)(g_ET + ((size_t)b*NS + s0 + s_local)*NQ + q0 + qp*2) = v;
    }
}

// ---------------- Kernel 3: row sums -> g_inv + normalized weights. Grid 256. ----------------
__global__ void __launch_bounds__(128) rowsum_kernel(float* __restrict__ out_w)
{
    const int tid  = threadIdx.x;
    const int lane = tid & 31;
    const int row  = blockIdx.x*4 + (tid >> 5);

    const float4* src = (const float4*)(g_E + (size_t)row*NS);
    float4 v[8];
    float s = 0.f;
    #pragma unroll
    for (int i = 0; i < 8; i++) {
        v[i] = src[lane + 32*i];
        s += (v[i].x + v[i].y) + (v[i].z + v[i].w);
    }
    #pragma unroll
    for (int o = 16; o > 0; o >>= 1) s += __shfl_xor_sync(0xffffffffu, s, o);
    const float inv = 1.0f / s;
    if (lane == 0) g_inv[row] = inv;

    float4* dst = (float4*)(out_w + (size_t)row*NS);
    #pragma unroll
    for (int i = 0; i < 8; i++) {
        v[i].x *= inv; v[i].y *= inv; v[i].z *= inv; v[i].w *= inv;
        dst[lane + 32*i] = v[i];
    }
}

// ---------------- Kernel 4: pgemm — split-s x16, forced 2 blocks/SM ----------------
// Grid 256 = 8 qt * 2 hh * 16 sc. 512 thr, 64KB smem, 8q x 4h thread tile.
// __launch_bounds__(512, 2): cap regs at 64 so 2 blocks co-reside (32 warps/SM).
__global__ void __launch_bounds__(512, 2) pgemm_kernel(const float* __restrict__ kv)
{
    extern __shared__ float ps[];
    float* kvs = ps;                    // 2 * 32*128
    float* Es  = ps + 2*SK2*128;        // 2 * 32*128

    const int tid = threadIdx.x;
    const int bid = blockIdx.x;
    const int sc  = bid & 15;
    const int hh  = (bid >> 4) & 1;
    const int qt  = bid >> 5;           // 0..7
    const int row0 = qt * 128;
    const int b   = qt >> 2;
    const int s0  = sc * 64;
    const int qcol = (qt & 3) * 128;    // q offset within batch

    const float* kvg = kv   + ((size_t)b*NS + s0)*KVH + hh*128;
    const float* Eg  = g_ET + ((size_t)b*NS + s0)*NQ + qcol;

    const int tx = tid & 31;            // h quad
    const int ty = tid >> 5;            // q octet

    #define ISSUE2(c, buf) { \
        _Pragma("unroll") for (int j = 0; j < 2; j++) { \
            int i = tid + 512*j; int s = i >> 5, h4 = i & 31; \
            cp16(kvs + (buf)*SK2*128 + s*128 + h4*4, \
                 kvg + (size_t)((c)*SK2 + s)*KVH + h4*4); } \
        _Pragma("unroll") for (int j = 0; j < 2; j++) { \
            int i = tid + 512*j; int s = i >> 5, q4 = i & 31; \
            cp16(Es + (buf)*SK2*128 + s*128 + q4*4, \
                 Eg + (size_t)((c)*SK2 + s)*NQ + q4*4); } \
        cp_commit(); }

    ISSUE2(0, 0);
    ISSUE2(1, 1);

    float2 acc[8][2];
    #pragma unroll
    for (int i = 0; i < 8; i++) { acc[i][0] = make_float2(0.f,0.f); acc[i][1] = make_float2(0.f,0.f); }

    #pragma unroll
    for (int c = 0; c < 2; c++) {
        if (c == 0) cp_wait1(); else cp_wait0();
        __syncthreads();
        const float* kvb = kvs + c*SK2*128;
        const float* Eb  = Es  + c*SK2*128;
        #pragma unroll 8
        for (int k = 0; k < SK2; k++) {
            float4 k4 = ((const float4*)(kvb + k*128))[tx];
            float4 e0 = ((const float4*)(Eb  + k*128))[ty*2];
            float4 e1 = ((const float4*)(Eb  + k*128))[ty*2 + 1];
            float2 kp0 = make_float2(k4.x, k4.y);
            float2 kp1 = make_float2(k4.z, k4.w);
            float ev[8] = { e0.x, e0.y, e0.z, e0.w, e1.x, e1.y, e1.z, e1.w };
            #pragma unroll
            for (int qi = 0; qi < 8; qi++) {
                float2 eb = make_float2(ev[qi], ev[qi]);
                acc[qi][0] = ffma2(kp0, eb, acc[qi][0]);
                acc[qi][1] = ffma2(kp1, eb, acc[qi][1]);
            }
        }
        __syncthreads();
    }

    float* pb = g_part + ((size_t)sc*(NB*NQ) + row0 + ty*8)*KVH + hh*128 + tx*4;
    #pragma unroll
    for (int qi = 0; qi < 8; qi++)
        *(float4*)(pb + (size_t)qi*KVH) =
            make_float4(acc[qi][0].x, acc[qi][0].y, acc[qi][1].x, acc[qi][1].y);
    #undef ISSUE2
}

// ---------------- Kernel 5: combine 16 partials + normalize ----------------
__global__ void __launch_bounds__(256) combine_kernel(float* __restrict__ out_o)
{
    const int idx = blockIdx.x*256 + threadIdx.x;
    const int row = idx >> 6;
    const float inv = g_inv[row];
    float4 s = make_float4(0.f,0.f,0.f,0.f);
    #pragma unroll
    for (int c = 0; c < NSC; c++) {
        float4 p = ((const float4*)g_part)[(size_t)c*(NB*NQ*KVH/4) + idx];
        s.x += p.x; s.y += p.y; s.z += p.z; s.w += p.w;
    }
    s.x *= inv; s.y *= inv; s.z *= inv; s.w *= inv;
    ((float4*)out_o)[idx] = s;
}

extern "C" void kernel_launch(void* const* d_in, const int* in_sizes, int n_in,
                              void* d_out, int out_size)
{
    const float* kv  = (const float*)d_in[0];
    const float* qy  = (const float*)d_in[1];
    const float* Wkv = (const float*)d_in[2];
    const float* bkv = (const float*)d_in[3];
    const float* Wq  = (const float*)d_in[4];
    const float* bq  = (const float*)d_in[5];
    const float* wv  = (const float*)d_in[6];
    const float* bv  = (const float*)d_in[7];

    float* out_o = (float*)d_out;
    float* out_w = out_o + NB*NQ*KVH;

    const int pg_smem = 4*SK2*128*4;    // 64KB

    // one-time setup (first call is the uncaptured correctness run)
    static cudaStream_t s1 = nullptr;
    static cudaEvent_t evS = nullptr, evJ = nullptr;
    if (!s1) {
        cudaStreamCreateWithFlags(&s1, cudaStreamNonBlocking);
        cudaEventCreateWithFlags(&evS, cudaEventDisableTiming);
        cudaEventCreateWithFlags(&evJ, cudaEventDisableTiming);
        cudaFuncSetAttribute(pgemm_kernel, cudaFuncAttributeMaxDynamicSharedMemorySize, pg_smem);
    }

    proj_kernel    <<<384, 256>>>(kv, qy, Wkv, Wq);
    proj_fix_kernel<<<384, 256>>>(bkv, bq);
    score_kernel   <<<2048, 256>>>(wv, bv);          // runs alone (MUFU floor)

    // after score: pgemm on s1, rowsum on default — complementary pipes
    cudaEventRecord(evS, 0);
    cudaStreamWaitEvent(s1, evS, 0);
    pgemm_kernel <<<256, 512, pg_smem, s1>>>(kv);
    rowsum_kernel<<<256, 128>>>(out_w);

    // join
    cudaEventRecord(evJ, s1);
    cudaStreamWaitEvent((cudaStream_t)0, evJ, 0);
    combine_kernel<<<256, 256>>>(out_o);
}

// round 13
// speedup vs baseline: 1.1006x; 1.1006x over previous
#include <cuda_runtime.h>

#define ATT_H 128
#define KVH   256
#define NB    2
#define NS    1024
#define NQ    512
#define SK2   32
#define NSC   16                        // pgemm split-s count
#define NROWS (NB*NS + NB*NQ)           // 3072 projection rows

// scratch (no allocations allowed)
__device__ float g_pp  [2*NROWS*ATT_H]; // proj k-split partials (score reads both halves)
__device__ float g_E   [NB*NQ*NS];      // [b][q][s] raw exp(score)
__device__ float g_ET  [NB*NS*NQ];      // [b][s][q] transposed copy
__device__ float g_part[NSC*NB*NQ*KVH]; // split-s partial GEMM results
__device__ float g_inv [NB*NQ];

__device__ __forceinline__ float fast_tanh(float x){ float y; asm("tanh.approx.f32 %0, %1;" : "=f"(y) : "f"(x)); return y; }
__device__ __forceinline__ float fast_ex2 (float x){ float y; asm("ex2.approx.f32 %0, %1;"  : "=f"(y) : "f"(x)); return y; }

__device__ __forceinline__ float2 ffma2(float2 a, float2 b, float2 c) {
    float2 d;
    asm("fma.rn.f32x2 %0, %1, %2, %3;"
        : "=l"(reinterpret_cast<unsigned long long&>(d))
        : "l"(reinterpret_cast<unsigned long long&>(a)),
          "l"(reinterpret_cast<unsigned long long&>(b)),
          "l"(reinterpret_cast<unsigned long long&>(c)));
    return d;
}

__device__ __forceinline__ void cp16(void* dst, const void* src) {
    unsigned d = (unsigned)__cvta_generic_to_shared(dst);
    asm volatile("cp.async.cg.shared.global [%0], [%1], 16;" :: "r"(d), "l"(src));
}
__device__ __forceinline__ void cp_commit() { asm volatile("cp.async.commit_group;"); }
__device__ __forceinline__ void cp_wait0()  { asm volatile("cp.async.wait_group 0;" ::: "memory"); }
__device__ __forceinline__ void cp_wait1()  { asm volatile("cp.async.wait_group 1;" ::: "memory"); }

// ---------------- Kernel 1: proj partials, k-split x2, 256 thr, 4r x 2c tile ----------------
__global__ void __launch_bounds__(256) proj_kernel(
    const float* __restrict__ kv, const float* __restrict__ qy,
    const float* __restrict__ Wkv, const float* __restrict__ Wq)
{
    __shared__ float w_sh [64*64];
    __shared__ float in_T [64*34];

    const int tid = threadIdx.x;
    const int rb  = blockIdx.x;       // 384 = 96 rowblk * 2 ch * 2 kh
    const int kh  = rb & 1;
    const int ch  = (rb >> 1) & 1;
    const int row0g = (rb >> 2) * 32;

    const float *in, *W;
    if (row0g < NB*NS) { in = kv + (size_t)row0g*256;           W = Wkv; }
    else               { in = qy + (size_t)(row0g - NB*NS)*256; W = Wq;  }
    in += kh*128;
    W  += (size_t)kh*128*128;

    const int tx = tid & 31;
    const int ty = tid >> 5;

    float2 acc[4];
    #pragma unroll
    for (int i = 0; i < 4; i++) acc[i] = make_float2(0.f, 0.f);

    float4 wr[4], ir[2];
    #pragma unroll
    for (int j = 0; j < 4; j++) {
        int f4 = tid + 256*j; int kk = f4 >> 4, c4 = f4 & 15;
        wr[j] = *(const float4*)(W + (size_t)kk*128 + ch*64 + c4*4);
    }
    #pragma unroll
    for (int j = 0; j < 2; j++) {
        int f4 = tid + 256*j; int r = f4 >> 4, k4 = f4 & 15;
        ir[j] = *(const float4*)(in + (size_t)r*256 + k4*4);
    }

    for (int kc = 0; kc < 2; kc++) {
        #pragma unroll
        for (int j = 0; j < 4; j++) {
            int f4 = tid + 256*j; int kk = f4 >> 4, c4 = f4 & 15;
            ((float4*)w_sh)[kk*16 + c4] = wr[j];
        }
        #pragma unroll
        for (int j = 0; j < 2; j++) {
            int f4 = tid + 256*j; int r = f4 >> 4, k4 = f4 & 15;
            in_T[(k4*4+0)*34 + r] = ir[j].x;
            in_T[(k4*4+1)*34 + r] = ir[j].y;
            in_T[(k4*4+2)*34 + r] = ir[j].z;
            in_T[(k4*4+3)*34 + r] = ir[j].w;
        }
        __syncthreads();
        if (kc < 1) {
            #pragma unroll
            for (int j = 0; j < 4; j++) {
                int f4 = tid + 256*j; int kk = f4 >> 4, c4 = f4 & 15;
                wr[j] = *(const float4*)(W + (size_t)(64 + kk)*128 + ch*64 + c4*4);
            }
            #pragma unroll
            for (int j = 0; j < 2; j++) {
                int f4 = tid + 256*j; int r = f4 >> 4, k4 = f4 & 15;
                ir[j] = *(const float4*)(in + (size_t)r*256 + 64 + k4*4);
            }
        }
        #pragma unroll 8
        for (int kk = 0; kk < 64; kk++) {
            float2 w2  = *(const float2*)&w_sh[kk*64 + tx*2];
            float2 i01 = *(const float2*)&in_T[kk*34 + ty*4];
            float2 i23 = *(const float2*)&in_T[kk*34 + ty*4 + 2];
            acc[0] = ffma2(w2, make_float2(i01.x, i01.x), acc[0]);
            acc[1] = ffma2(w2, make_float2(i01.y, i01.y), acc[1]);
            acc[2] = ffma2(w2, make_float2(i23.x, i23.x), acc[2]);
            acc[3] = ffma2(w2, make_float2(i23.y, i23.y), acc[3]);
        }
        __syncthreads();
    }

    float* outp = g_pp + (size_t)kh*NROWS*ATT_H + (size_t)(row0g + ty*4)*ATT_H + ch*64 + tx*2;
    #pragma unroll
    for (int ri = 0; ri < 4; ri++)
        *(float2*)(outp + (size_t)ri*ATT_H) = acc[ri];
}

// ---------------- Kernel 2: score (monolithic), reads g_pp halves directly ----------------
// pk = pp0+pp1 (no bias); pq = pp0+pp1 + (bkv+bq). Grid 2048.
__global__ void __launch_bounds__(256) score_kernel(
    const float* __restrict__ wv_g, const float* __restrict__ bv_g,
    const float* __restrict__ bkv_g, const float* __restrict__ bq_g)
{
    __shared__ float4 pk_sh[64*33];
    __shared__ float4 pq_sh[8*32];
    __shared__ float4 wv_sh[32];
    __shared__ float  ET_sh[64*9];     // [s_local][q] pad 9

    const int tid = threadIdx.x;
    const int bid = blockIdx.x;
    const int st  = bid & 15;
    const int qt  = bid >> 4;
    const int b   = qt >> 6;
    const int q0  = (qt & 63) * 8;
    const int s0  = st * 64;

    const float4* pp0 = (const float4*)g_pp;
    const float4* pp1 = pp0 + NROWS*(ATT_H/4);

    // pq: 8 rows (q) x 32 f4, with combined bias
    {
        int q = tid >> 5, a4 = tid & 31;
        size_t r = (size_t)(NB*NS + b*NQ + q0 + q)*32 + a4;
        float4 v0 = pp0[r], v1 = pp1[r];
        float4 bk = ((const float4*)bkv_g)[a4];
        float4 bq = ((const float4*)bq_g)[a4];
        pq_sh[q*32 + a4] = make_float4(v0.x+v1.x+bk.x+bq.x, v0.y+v1.y+bk.y+bq.y,
                                       v0.z+v1.z+bk.z+bq.z, v0.w+v1.w+bk.w+bq.w);
    }
    if (tid < 32) wv_sh[tid] = ((const float4*)wv_g)[tid];
    // pk: 64 rows (s) x 32 f4
    #pragma unroll
    for (int i = 0; i < 8; i++) {
        int f4 = tid + 256*i;
        int row = f4 >> 5, c4 = f4 & 31;
        size_t r = (size_t)(b*NS + s0 + row)*32 + c4;
        float4 v0 = pp0[r], v1 = pp1[r];
        pk_sh[row*33 + c4] = make_float4(v0.x+v1.x, v0.y+v1.y, v0.z+v1.z, v0.w+v1.w);
    }
    __syncthreads();

    const float bv = __ldg(bv_g);
    const int sl = tid & 63;
    const int qq = tid >> 6;

    float acc0 = 0.f, acc1 = 0.f;
    const float4* pkp  = pk_sh + sl*33;
    const float4* pq0p = pq_sh + (2*qq    )*32;
    const float4* pq1p = pq_sh + (2*qq + 1)*32;

    #pragma unroll 8
    for (int a4 = 0; a4 < 32; a4++) {
        float4 pk = pkp[a4];
        float4 w  = wv_sh[a4];
        float4 p0 = pq0p[a4];
        float4 p1 = pq1p[a4];
        acc0 += w.x * fast_tanh(pk.x + p0.x);
        acc0 += w.y * fast_tanh(pk.y + p0.y);
        acc0 += w.z * fast_tanh(pk.z + p0.z);
        acc0 += w.w * fast_tanh(pk.w + p0.w);
        acc1 += w.x * fast_tanh(pk.x + p1.x);
        acc1 += w.y * fast_tanh(pk.y + p1.y);
        acc1 += w.z * fast_tanh(pk.z + p1.z);
        acc1 += w.w * fast_tanh(pk.w + p1.w);
    }
    float e0 = fast_ex2((acc0 + bv) * 1.44269504f);
    float e1 = fast_ex2((acc1 + bv) * 1.44269504f);

    // row-major write (for rowsum/out_w)
    float* Eout = g_E + (size_t)(b*NQ + q0 + 2*qq)*NS + s0 + sl;
    Eout[0]  = e0;
    Eout[NS] = e1;

    // transposed write (for pgemm): stage in smem, then coalesced float2
    ET_sh[sl*9 + 2*qq]     = e0;
    ET_sh[sl*9 + 2*qq + 1] = e1;
    __syncthreads();
    {
        int s_local = tid >> 2, qp = tid & 3;
        float2 v = make_float2(ET_sh[s_local*9 + qp*2], ET_sh[s_local*9 + qp*2 + 1]);
        *(float2*)(g_ET + ((size_t)b*NS + s0 + s_local)*NQ + q0 + qp*2) = v;
    }
}

// ---------------- Kernel 3: row sums -> g_inv + normalized weights. Grid 256. ----------------
__global__ void __launch_bounds__(128) rowsum_kernel(float* __restrict__ out_w)
{
    const int tid  = threadIdx.x;
    const int lane = tid & 31;
    const int row  = blockIdx.x*4 + (tid >> 5);

    const float4* src = (const float4*)(g_E + (size_t)row*NS);
    float4 v[8];
    float s = 0.f;
    #pragma unroll
    for (int i = 0; i < 8; i++) {
        v[i] = src[lane + 32*i];
        s += (v[i].x + v[i].y) + (v[i].z + v[i].w);
    }
    #pragma unroll
    for (int o = 16; o > 0; o >>= 1) s += __shfl_xor_sync(0xffffffffu, s, o);
    const float inv = 1.0f / s;
    if (lane == 0) g_inv[row] = inv;

    float4* dst = (float4*)(out_w + (size_t)row*NS);
    #pragma unroll
    for (int i = 0; i < 8; i++) {
        v[i].x *= inv; v[i].y *= inv; v[i].z *= inv; v[i].w *= inv;
        dst[lane + 32*i] = v[i];
    }
}

// ---------------- Kernel 4: pgemm — 256-thr blocks, natural regs, ~3 blocks/SM ----------------
// Grid 512 = 16 qt(64q) * 2 hh * 16 sc(64s). SK=32, 2 chunks, depth-2. 48KB smem.
// Thread tile 8q x 4h (same proven inner loop as the 64.2us config).
__global__ void __launch_bounds__(256) pgemm_kernel(const float* __restrict__ kv)
{
    extern __shared__ float ps[];
    float* kvs = ps;                    // 2 * 32*128 = 8192
    float* Es  = ps + 2*SK2*128;        // 2 * 32*64  = 4096

    const int tid = threadIdx.x;
    const int bid = blockIdx.x;
    const int sc  = bid & 15;
    const int hh  = (bid >> 4) & 1;
    const int qt  = bid >> 5;           // 0..15
    const int row0 = qt * 64;
    const int b   = qt >> 3;
    const int qcol = (qt & 7) * 64;
    const int s0  = sc * 64;

    const float* kvg = kv   + ((size_t)b*NS + s0)*KVH + hh*128;
    const float* Eg  = g_ET + ((size_t)b*NS + s0)*NQ + qcol;

    const int tx = tid & 31;            // h quad
    const int ty = tid >> 5;            // q octet (warp-uniform)

    #define ISSUE2(c, buf) { \
        _Pragma("unroll") for (int j = 0; j < 4; j++) { \
            int i = tid + 256*j; int s = i >> 5, h4 = i & 31; \
            cp16(kvs + (buf)*SK2*128 + s*128 + h4*4, \
                 kvg + (size_t)((c)*SK2 + s)*KVH + h4*4); } \
        _Pragma("unroll") for (int j = 0; j < 2; j++) { \
            int i = tid + 256*j; int s = i >> 4, q4 = i & 15; \
            cp16(Es + (buf)*SK2*64 + s*64 + q4*4, \
                 Eg + (size_t)((c)*SK2 + s)*NQ + q4*4); } \
        cp_commit(); }

    ISSUE2(0, 0);
    ISSUE2(1, 1);

    float2 acc[8][2];
    #pragma unroll
    for (int i = 0; i < 8; i++) { acc[i][0] = make_float2(0.f,0.f); acc[i][1] = make_float2(0.f,0.f); }

    #pragma unroll
    for (int c = 0; c < 2; c++) {
        if (c == 0) cp_wait1(); else cp_wait0();
        __syncthreads();
        const float* kvb = kvs + c*SK2*128;
        const float* Eb  = Es  + c*SK2*64;
        #pragma unroll 8
        for (int k = 0; k < SK2; k++) {
            float4 k4 = ((const float4*)(kvb + k*128))[tx];
            float4 e0 = ((const float4*)(Eb  + k*64))[ty*2];
            float4 e1 = ((const float4*)(Eb  + k*64))[ty*2 + 1];
            float2 kp0 = make_float2(k4.x, k4.y);
            float2 kp1 = make_float2(k4.z, k4.w);
            float ev[8] = { e0.x, e0.y, e0.z, e0.w, e1.x, e1.y, e1.z, e1.w };
            #pragma unroll
            for (int qi = 0; qi < 8; qi++) {
                float2 eb = make_float2(ev[qi], ev[qi]);
                acc[qi][0] = ffma2(kp0, eb, acc[qi][0]);
                acc[qi][1] = ffma2(kp1, eb, acc[qi][1]);
            }
        }
        __syncthreads();
    }

    float* pb = g_part + ((size_t)sc*(NB*NQ) + row0 + ty*8)*KVH + hh*128 + tx*4;
    #pragma unroll
    for (int qi = 0; qi < 8; qi++)
        *(float4*)(pb + (size_t)qi*KVH) =
            make_float4(acc[qi][0].x, acc[qi][0].y, acc[qi][1].x, acc[qi][1].y);
    #undef ISSUE2
}

// ---------------- Kernel 5: combine 16 partials + normalize (L2-resident) ----------------
__global__ void __launch_bounds__(256) combine_kernel(float* __restrict__ out_o)
{
    const int idx = blockIdx.x*256 + threadIdx.x;
    const int row = idx >> 6;
    const float inv = g_inv[row];
    float4 s = make_float4(0.f,0.f,0.f,0.f);
    #pragma unroll
    for (int c = 0; c < NSC; c++) {
        float4 p = ((const float4*)g_part)[(size_t)c*(NB*NQ*KVH/4) + idx];
        s.x += p.x; s.y += p.y; s.z += p.z; s.w += p.w;
    }
    s.x *= inv; s.y *= inv; s.z *= inv; s.w *= inv;
    ((float4*)out_o)[idx] = s;
}

extern "C" void kernel_launch(void* const* d_in, const int* in_sizes, int n_in,
                              void* d_out, int out_size)
{
    const float* kv  = (const float*)d_in[0];
    const float* qy  = (const float*)d_in[1];
    const float* Wkv = (const float*)d_in[2];
    const float* bkv = (const float*)d_in[3];
    const float* Wq  = (const float*)d_in[4];
    const float* bq  = (const float*)d_in[5];
    const float* wv  = (const float*)d_in[6];
    const float* bv  = (const float*)d_in[7];

    float* out_o = (float*)d_out;
    float* out_w = out_o + NB*NQ*KVH;

    const int pg_smem = (2*SK2*128 + 2*SK2*64) * 4;   // 48KB

    // one-time setup (first call is the uncaptured correctness run)
    static cudaStream_t s1 = nullptr;
    static cudaEvent_t evS = nullptr, evJ = nullptr;
    if (!s1) {
        cudaStreamCreateWithFlags(&s1, cudaStreamNonBlocking);
        cudaEventCreateWithFlags(&evS, cudaEventDisableTiming);
        cudaEventCreateWithFlags(&evJ, cudaEventDisableTiming);
        cudaFuncSetAttribute(pgemm_kernel, cudaFuncAttributeMaxDynamicSharedMemorySize, pg_smem);
    }

    proj_kernel <<<384, 256>>>(kv, qy, Wkv, Wq);
    score_kernel<<<2048, 256>>>(wv, bv, bkv, bq);     // reads g_pp halves + biases directly

    // after score: pgemm on s1, rowsum on default — complementary pipes
    cudaEventRecord(evS, 0);
    cudaStreamWaitEvent(s1, evS, 0);
    pgemm_kernel <<<512, 256, pg_smem, s1>>>(kv);
    rowsum_kernel<<<256, 128>>>(out_w);

    // join
    cudaEventRecord(evJ, s1);
    cudaStreamWaitEvent((cudaStream_t)0, evJ, 0);
    combine_kernel<<<256, 256>>>(out_o);
}

// round 14
// speedup vs baseline: 1.1358x; 1.0320x over previous
#include <cuda_runtime.h>

#define ATT_H 128
#define KVH   256
#define NB    2
#define NS    1024
#define NQ    512
#define SK2   32
#define NSC   16                        // pgemm split-s count
#define NROWS (NB*NS + NB*NQ)           // 3072 projection rows

// scratch (no allocations allowed)
__device__ float g_pp  [2*NROWS*ATT_H]; // proj k-split partials (score reads both halves)
__device__ float g_E   [NB*NQ*NS];      // [b][q][s] raw exp(score)
__device__ float g_ET  [NB*NS*NQ];      // [b][s][q] transposed copy
__device__ float g_part[NSC*NB*NQ*KVH]; // split-s partial GEMM results
__device__ float g_inv [NB*NQ];

__device__ __forceinline__ float fast_tanh(float x){ float y; asm("tanh.approx.f32 %0, %1;" : "=f"(y) : "f"(x)); return y; }
__device__ __forceinline__ float fast_ex2 (float x){ float y; asm("ex2.approx.f32 %0, %1;"  : "=f"(y) : "f"(x)); return y; }

__device__ __forceinline__ float2 ffma2(float2 a, float2 b, float2 c) {
    float2 d;
    asm("fma.rn.f32x2 %0, %1, %2, %3;"
        : "=l"(reinterpret_cast<unsigned long long&>(d))
        : "l"(reinterpret_cast<unsigned long long&>(a)),
          "l"(reinterpret_cast<unsigned long long&>(b)),
          "l"(reinterpret_cast<unsigned long long&>(c)));
    return d;
}

__device__ __forceinline__ void cp16(void* dst, const void* src) {
    unsigned d = (unsigned)__cvta_generic_to_shared(dst);
    asm volatile("cp.async.cg.shared.global [%0], [%1], 16;" :: "r"(d), "l"(src));
}
__device__ __forceinline__ void cp_commit() { asm volatile("cp.async.commit_group;"); }
__device__ __forceinline__ void cp_wait0()  { asm volatile("cp.async.wait_group 0;" ::: "memory"); }
__device__ __forceinline__ void cp_wait1()  { asm volatile("cp.async.wait_group 1;" ::: "memory"); }

// ---------------- Kernel 1: proj partials — cp.async pipelined ----------------
// Block: 32 rows x 64 cols (ch) x 128 k (kh), 256 thr, thread tile 4r x 2c.
// W: cp.async depth-2, 32-k chunks. in: LDG.128 one chunk ahead + transposed STS.
__global__ void __launch_bounds__(256) proj_kernel(
    const float* __restrict__ kv, const float* __restrict__ qy,
    const float* __restrict__ Wkv, const float* __restrict__ Wq)
{
    __shared__ float Wb [2][32*64];   // [kk][c] per chunk, 8KB each
    __shared__ float inT[2][32*34];   // [kk][r] transposed, pad 34

    const int tid = threadIdx.x;
    const int rb  = blockIdx.x;       // 384 = 96 rowblk * 2 ch * 2 kh
    const int kh  = rb & 1;
    const int ch  = (rb >> 1) & 1;
    const int row0g = (rb >> 2) * 32;

    const float *in, *W;
    if (row0g < NB*NS) { in = kv + (size_t)row0g*256;           W = Wkv; }
    else               { in = qy + (size_t)(row0g - NB*NS)*256; W = Wq;  }
    in += kh*128;
    W  += (size_t)kh*128*128 + ch*64;

    // loader identities
    const int wk  = tid >> 3;         // W: not used (W by f4 below)
    const int ir  = tid >> 3;         // in: row 0..31
    const int ik4 = tid & 7;          // in: k-quad 0..7
    (void)wk;

    // W chunk stage: 32k x 64c = 512 f4, 2 per thread
    #define CPW(c, buf) { \
        _Pragma("unroll") for (int j = 0; j < 2; j++) { \
            int idx = tid + 256*j; int kk = idx >> 4, c4 = idx & 15; \
            cp16(&Wb[buf][kk*64 + c4*4], W + (size_t)((c)*32 + kk)*128 + c4*4); } \
        cp_commit(); }

    #define LDGIN(c) (*(const float4*)(in + (size_t)ir*256 + (c)*32 + ik4*4))

    #define STSIN(c, v) { \
        inT[(c)&1][(ik4*4+0)*34 + ir] = (v).x; \
        inT[(c)&1][(ik4*4+1)*34 + ir] = (v).y; \
        inT[(c)&1][(ik4*4+2)*34 + ir] = (v).z; \
        inT[(c)&1][(ik4*4+3)*34 + ir] = (v).w; }

    const int tx = tid & 31;          // c pair
    const int ty = tid >> 5;          // row quad (warp-uniform)

    float2 acc[4];
    #pragma unroll
    for (int i = 0; i < 4; i++) acc[i] = make_float2(0.f, 0.f);

    // prologue
    CPW(0, 0);
    float4 iv = LDGIN(0);
    CPW(1, 1);
    STSIN(0, iv);
    cp_wait1();
    __syncthreads();

    for (int kc = 0; kc < 4; kc++) {
        const int buf = kc & 1;
        if (kc < 3) iv = LDGIN(kc + 1);

        const float* Wp = Wb[buf];
        const float* Ip = inT[buf];
        #pragma unroll 8
        for (int kk = 0; kk < 32; kk++) {
            float2 w2  = *(const float2*)&Wp[kk*64 + tx*2];
            float2 i01 = *(const float2*)&Ip[kk*34 + ty*4];
            float2 i23 = *(const float2*)&Ip[kk*34 + ty*4 + 2];
            acc[0] = ffma2(w2, make_float2(i01.x, i01.x), acc[0]);
            acc[1] = ffma2(w2, make_float2(i01.y, i01.y), acc[1]);
            acc[2] = ffma2(w2, make_float2(i23.x, i23.x), acc[2]);
            acc[3] = ffma2(w2, make_float2(i23.y, i23.y), acc[3]);
        }
        __syncthreads();                       // everyone done reading buf

        if (kc < 2) CPW(kc + 2, buf);          // refill W into just-freed buf
        if (kc < 3) {
            STSIN(kc + 1, iv);                 // in chunk kc+1 -> inT[buf^1]
            if (kc == 2) cp_wait0(); else cp_wait1();   // W chunk kc+1 resident
            __syncthreads();
        }
    }

    float* outp = g_pp + (size_t)kh*NROWS*ATT_H + (size_t)(row0g + ty*4)*ATT_H + ch*64 + tx*2;
    #pragma unroll
    for (int ri = 0; ri < 4; ri++)
        *(float2*)(outp + (size_t)ri*ATT_H) = acc[ri];
    #undef CPW
    #undef LDGIN
    #undef STSIN
}

// ---------------- Kernel 2: score (monolithic), reads g_pp halves directly ----------------
__global__ void __launch_bounds__(256) score_kernel(
    const float* __restrict__ wv_g, const float* __restrict__ bv_g,
    const float* __restrict__ bkv_g, const float* __restrict__ bq_g)
{
    __shared__ float4 pk_sh[64*33];
    __shared__ float4 pq_sh[8*32];
    __shared__ float4 wv_sh[32];
    __shared__ float  ET_sh[64*9];

    const int tid = threadIdx.x;
    const int bid = blockIdx.x;
    const int st  = bid & 15;
    const int qt  = bid >> 4;
    const int b   = qt >> 6;
    const int q0  = (qt & 63) * 8;
    const int s0  = st * 64;

    const float4* pp0 = (const float4*)g_pp;
    const float4* pp1 = pp0 + NROWS*(ATT_H/4);

    {
        int q = tid >> 5, a4 = tid & 31;
        size_t r = (size_t)(NB*NS + b*NQ + q0 + q)*32 + a4;
        float4 v0 = pp0[r], v1 = pp1[r];
        float4 bk = ((const float4*)bkv_g)[a4];
        float4 bq = ((const float4*)bq_g)[a4];
        pq_sh[q*32 + a4] = make_float4(v0.x+v1.x+bk.x+bq.x, v0.y+v1.y+bk.y+bq.y,
                                       v0.z+v1.z+bk.z+bq.z, v0.w+v1.w+bk.w+bq.w);
    }
    if (tid < 32) wv_sh[tid] = ((const float4*)wv_g)[tid];
    #pragma unroll
    for (int i = 0; i < 8; i++) {
        int f4 = tid + 256*i;
        int row = f4 >> 5, c4 = f4 & 31;
        size_t r = (size_t)(b*NS + s0 + row)*32 + c4;
        float4 v0 = pp0[r], v1 = pp1[r];
        pk_sh[row*33 + c4] = make_float4(v0.x+v1.x, v0.y+v1.y, v0.z+v1.z, v0.w+v1.w);
    }
    __syncthreads();

    const float bv = __ldg(bv_g);
    const int sl = tid & 63;
    const int qq = tid >> 6;

    float acc0 = 0.f, acc1 = 0.f;
    const float4* pkp  = pk_sh + sl*33;
    const float4* pq0p = pq_sh + (2*qq    )*32;
    const float4* pq1p = pq_sh + (2*qq + 1)*32;

    #pragma unroll 8
    for (int a4 = 0; a4 < 32; a4++) {
        float4 pk = pkp[a4];
        float4 w  = wv_sh[a4];
        float4 p0 = pq0p[a4];
        float4 p1 = pq1p[a4];
        acc0 += w.x * fast_tanh(pk.x + p0.x);
        acc0 += w.y * fast_tanh(pk.y + p0.y);
        acc0 += w.z * fast_tanh(pk.z + p0.z);
        acc0 += w.w * fast_tanh(pk.w + p0.w);
        acc1 += w.x * fast_tanh(pk.x + p1.x);
        acc1 += w.y * fast_tanh(pk.y + p1.y);
        acc1 += w.z * fast_tanh(pk.z + p1.z);
        acc1 += w.w * fast_tanh(pk.w + p1.w);
    }
    float e0 = fast_ex2((acc0 + bv) * 1.44269504f);
    float e1 = fast_ex2((acc1 + bv) * 1.44269504f);

    float* Eout = g_E + (size_t)(b*NQ + q0 + 2*qq)*NS + s0 + sl;
    Eout[0]  = e0;
    Eout[NS] = e1;

    ET_sh[sl*9 + 2*qq]     = e0;
    ET_sh[sl*9 + 2*qq + 1] = e1;
    __syncthreads();
    {
        int s_local = tid >> 2, qp = tid & 3;
        float2 v = make_float2(ET_sh[s_local*9 + qp*2], ET_sh[s_local*9 + qp*2 + 1]);
        *(float2*)(g_ET + ((size_t)b*NS + s0 + s_local)*NQ + q0 + qp*2) = v;
    }
}

// ---------------- Kernel 3: row sums -> g_inv + normalized weights. Grid 256. ----------------
__global__ void __launch_bounds__(128) rowsum_kernel(float* __restrict__ out_w)
{
    const int tid  = threadIdx.x;
    const int lane = tid & 31;
    const int row  = blockIdx.x*4 + (tid >> 5);

    const float4* src = (const float4*)(g_E + (size_t)row*NS);
    float4 v[8];
    float s = 0.f;
    #pragma unroll
    for (int i = 0; i < 8; i++) {
        v[i] = src[lane + 32*i];
        s += (v[i].x + v[i].y) + (v[i].z + v[i].w);
    }
    #pragma unroll
    for (int o = 16; o > 0; o >>= 1) s += __shfl_xor_sync(0xffffffffu, s, o);
    const float inv = 1.0f / s;
    if (lane == 0) g_inv[row] = inv;

    float4* dst = (float4*)(out_w + (size_t)row*NS);
    #pragma unroll
    for (int i = 0; i < 8; i++) {
        v[i].x *= inv; v[i].y *= inv; v[i].z *= inv; v[i].w *= inv;
        dst[lane + 32*i] = v[i];
    }
}

// ---------------- Kernel 4: pgemm — 256-thr blocks, ~3 blocks/SM (R13 proven) ----------------
__global__ void __launch_bounds__(256) pgemm_kernel(const float* __restrict__ kv)
{
    extern __shared__ float ps[];
    float* kvs = ps;                    // 2 * 32*128
    float* Es  = ps + 2*SK2*128;        // 2 * 32*64

    const int tid = threadIdx.x;
    const int bid = blockIdx.x;
    const int sc  = bid & 15;
    const int hh  = (bid >> 4) & 1;
    const int qt  = bid >> 5;           // 0..15
    const int row0 = qt * 64;
    const int b   = qt >> 3;
    const int qcol = (qt & 7) * 64;
    const int s0  = sc * 64;

    const float* kvg = kv   + ((size_t)b*NS + s0)*KVH + hh*128;
    const float* Eg  = g_ET + ((size_t)b*NS + s0)*NQ + qcol;

    const int tx = tid & 31;
    const int ty = tid >> 5;

    #define ISSUE2(c, buf) { \
        _Pragma("unroll") for (int j = 0; j < 4; j++) { \
            int i = tid + 256*j; int s = i >> 5, h4 = i & 31; \
            cp16(kvs + (buf)*SK2*128 + s*128 + h4*4, \
                 kvg + (size_t)((c)*SK2 + s)*KVH + h4*4); } \
        _Pragma("unroll") for (int j = 0; j < 2; j++) { \
            int i = tid + 256*j; int s = i >> 4, q4 = i & 15; \
            cp16(Es + (buf)*SK2*64 + s*64 + q4*4, \
                 Eg + (size_t)((c)*SK2 + s)*NQ + q4*4); } \
        cp_commit(); }

    ISSUE2(0, 0);
    ISSUE2(1, 1);

    float2 acc[8][2];
    #pragma unroll
    for (int i = 0; i < 8; i++) { acc[i][0] = make_float2(0.f,0.f); acc[i][1] = make_float2(0.f,0.f); }

    #pragma unroll
    for (int c = 0; c < 2; c++) {
        if (c == 0) cp_wait1(); else cp_wait0();
        __syncthreads();
        const float* kvb = kvs + c*SK2*128;
        const float* Eb  = Es  + c*SK2*64;
        #pragma unroll 8
        for (int k = 0; k < SK2; k++) {
            float4 k4 = ((const float4*)(kvb + k*128))[tx];
            float4 e0 = ((const float4*)(Eb  + k*64))[ty*2];
            float4 e1 = ((const float4*)(Eb  + k*64))[ty*2 + 1];
            float2 kp0 = make_float2(k4.x, k4.y);
            float2 kp1 = make_float2(k4.z, k4.w);
            float ev[8] = { e0.x, e0.y, e0.z, e0.w, e1.x, e1.y, e1.z, e1.w };
            #pragma unroll
            for (int qi = 0; qi < 8; qi++) {
                float2 eb = make_float2(ev[qi], ev[qi]);
                acc[qi][0] = ffma2(kp0, eb, acc[qi][0]);
                acc[qi][1] = ffma2(kp1, eb, acc[qi][1]);
            }
        }
        __syncthreads();
    }

    float* pb = g_part + ((size_t)sc*(NB*NQ) + row0 + ty*8)*KVH + hh*128 + tx*4;
    #pragma unroll
    for (int qi = 0; qi < 8; qi++)
        *(float4*)(pb + (size_t)qi*KVH) =
            make_float4(acc[qi][0].x, acc[qi][0].y, acc[qi][1].x, acc[qi][1].y);
    #undef ISSUE2
}

// ---------------- Kernel 5: combine 16 partials + normalize (L2-resident) ----------------
__global__ void __launch_bounds__(256) combine_kernel(float* __restrict__ out_o)
{
    const int idx = blockIdx.x*256 + threadIdx.x;
    const int row = idx >> 6;
    const float inv = g_inv[row];
    float4 s = make_float4(0.f,0.f,0.f,0.f);
    #pragma unroll
    for (int c = 0; c < NSC; c++) {
        float4 p = ((const float4*)g_part)[(size_t)c*(NB*NQ*KVH/4) + idx];
        s.x += p.x; s.y += p.y; s.z += p.z; s.w += p.w;
    }
    s.x *= inv; s.y *= inv; s.z *= inv; s.w *= inv;
    ((float4*)out_o)[idx] = s;
}

extern "C" void kernel_launch(void* const* d_in, const int* in_sizes, int n_in,
                              void* d_out, int out_size)
{
    const float* kv  = (const float*)d_in[0];
    const float* qy  = (const float*)d_in[1];
    const float* Wkv = (const float*)d_in[2];
    const float* bkv = (const float*)d_in[3];
    const float* Wq  = (const float*)d_in[4];
    const float* bq  = (const float*)d_in[5];
    const float* wv  = (const float*)d_in[6];
    const float* bv  = (const float*)d_in[7];

    float* out_o = (float*)d_out;
    float* out_w = out_o + NB*NQ*KVH;

    const int pg_smem = (2*SK2*128 + 2*SK2*64) * 4;   // 48KB

    static cudaStream_t s1 = nullptr;
    static cudaEvent_t evS = nullptr, evJ = nullptr;
    if (!s1) {
        cudaStreamCreateWithFlags(&s1, cudaStreamNonBlocking);
        cudaEventCreateWithFlags(&evS, cudaEventDisableTiming);
        cudaEventCreateWithFlags(&evJ, cudaEventDisableTiming);
        cudaFuncSetAttribute(pgemm_kernel, cudaFuncAttributeMaxDynamicSharedMemorySize, pg_smem);
    }

    proj_kernel <<<384, 256>>>(kv, qy, Wkv, Wq);
    score_kernel<<<2048, 256>>>(wv, bv, bkv, bq);

    // after score: pgemm on s1, rowsum on default — complementary pipes
    cudaEventRecord(evS, 0);
    cudaStreamWaitEvent(s1, evS, 0);
    pgemm_kernel <<<512, 256, pg_smem, s1>>>(kv);
    rowsum_kernel<<<256, 128>>>(out_w);

    // join
    cudaEventRecord(evJ, s1);
    cudaStreamWaitEvent((cudaStream_t)0, evJ, 0);
    combine_kernel<<<256, 256>>>(out_o);
}